// round 17
// baseline (speedup 1.0000x reference)
#include <cuda_runtime.h>

#define NPTS 2048
#define KCAP 256
#define NTHREADS 256
#define ROWS_PER_BLOCK 2
#define WARPS_PER_ROW 4
#define CUT2 0.09f
#define EPSB 1e-3f
#define MWORDS 512    // 8 active-slot cells max * 64 words

#define MAX_OFFSET ((size_t)NPTS * KCAP * 4)

// Scratch (__device__ globals, allocation-free)
__device__ float4 g_sorted[NPTS];   // x-bucket-sorted points; .w = original j (bits)
__device__ int    g_bstart[257];    // bucket start offsets
__device__ int    g_flag = 0;       // sort-done gate (self-resetting each launch)
__device__ int    g_done = 0;       // finished-block counter (self-resetting)

__global__ __launch_bounds__(NTHREADS, 7)
void pb_fused_kernel(const float* __restrict__ pos, float* __restrict__ out) {
    __shared__ unsigned s_mask[ROWS_PER_BLOCK][MWORDS];           // 4 KB
    __shared__ unsigned short s_stage[ROWS_PER_BLOCK][KCAP];      // 1 KB
    __shared__ unsigned short s_ccode[ROWS_PER_BLOCK][8];
    __shared__ int s_wcnt[ROWS_PER_BLOCK][WARPS_PER_ROW];

    const int tid  = threadIdx.x;
    const int lane = tid & 31;
    const int w    = tid >> 5;
    const int r    = w >> 2;
    const int q    = w & 3;
    const unsigned lmask = (1u << lane) - 1u;

    // ================= Block 0: counting sort (s_mask aliased as scratch) ====
    if (blockIdx.x == 0) {
        int* sh = (int*)&s_mask[0][0];      // [0..255]=hist, [256..511]=cursor, [512..519]=wsum
        if (tid < 256) sh[tid] = 0;
        __syncthreads();

        float4 p[8]; int b[8];
#pragma unroll
        for (int rr = 0; rr < 8; rr++) {
            const int j = tid + rr * 256;
            const float xx = pos[3 * j], yy = pos[3 * j + 1], zz = pos[3 * j + 2];
            int bb = (int)(xx * 256.0f);
            bb = bb < 0 ? 0 : (bb > 255 ? 255 : bb);
            p[rr] = make_float4(xx, yy, zz, __int_as_float(j));
            b[rr] = bb;
            atomicAdd(&sh[bb], 1);
        }
        __syncthreads();

        {   // exclusive prefix over 256 histogram entries
            const int v = sh[tid];
            int incl = v;
#pragma unroll
            for (int d = 1; d < 32; d <<= 1) {
                const int t = __shfl_up_sync(0xFFFFFFFFu, incl, d);
                if (lane >= d) incl += t;
            }
            if (lane == 31) sh[512 + w] = incl;
            __syncthreads();
            int woff = 0;
            for (int k = 0; k < w; k++) woff += sh[512 + k];
            const int excl = woff + incl - v;
            __syncthreads();               // done reading hist before cursor overwrite order
            sh[256 + tid] = excl;
            g_bstart[tid] = excl;
            if (tid == 0) { g_bstart[256] = NPTS; out[MAX_OFFSET] = 0.0f; }
        }
        __syncthreads();

#pragma unroll
        for (int rr = 0; rr < 8; rr++) {
            const int dst = atomicAdd(&sh[256 + b[rr]], 1);
            g_sorted[dst] = p[rr];
        }
        __syncthreads();
        if (tid == 0) {
            __threadfence();
            atomicExch(&g_flag, 1);
        }
        __syncthreads();
    }

    // ================= Per-row prologue (independent of sorted data) =========
    const int i = blockIdx.x * ROWS_PER_BLOCK + r;
    const float pix = __ldg(&pos[3 * i]);
    const float piy = __ldg(&pos[3 * i + 1]);
    const float piz = __ldg(&pos[3 * i + 2]);

    // Per-dim shift feasibility (margin 1e-4 >> fp32 rounding); -1/+1 mutually exclusive.
    const bool okxm = pix < 0.30001f, okxp = pix > 0.69999f;
    const bool okym = piy < 0.30001f, okyp = piy > 0.69999f;
    const bool okzm = piz < 0.30001f, okzp = piz > 0.69999f;

    const int nx = 1 + okxm + okxp, ny = 1 + okym + okyp, nz = 1 + okzm + okzp;
    const int nA = nx * ny * nz;
    const bool hy = okym || okyp;
    const bool hz = okzm || okzp;
    const float fy = okym ? -1.0f : 1.0f;
    const float fz = okzm ? -1.0f : 1.0f;

    // slot -> canonical cell code table (slot order == ascending c; x fastest in both)
    if (q == 0) {
        bool act = false;
        if (lane < 27) {
            const int xi = lane % 3, yi = (lane / 3) % 3, zi = lane / 9;
            const bool ax = (xi == 1) || (xi == 0 && okxm) || (xi == 2 && okxp);
            const bool ay = (yi == 1) || (yi == 0 && okym) || (yi == 2 && okyp);
            const bool az = (zi == 1) || (zi == 0 && okzm) || (zi == 2 && okzp);
            act = ax && ay && az;
        }
        const unsigned b = __ballot_sync(0xFFFFFFFFu, act);
        if (act) s_ccode[r][__popc(b & lmask)] = (unsigned short)(lane << 11);
    }

    // Zero only this row's active words (the row's 4 warps cover nA*64 words)
    {
        unsigned* __restrict__ rm = s_mask[r];
        const int rowTid128 = tid & 127;
        for (int k = rowTid128; k < nA * 64; k += 128) rm[k] = 0u;
    }

    // ================= Gate: wait until the sort is published =================
    if (blockIdx.x != 0) {
        if (tid == 0) {
            while (atomicAdd(&g_flag, 0) == 0) __nanosleep(200);
            __threadfence();
        }
    }
    __syncthreads();   // orders prologue + gate for all threads

    // Ranks within ascending active lists -> slot = (posz*ny+posy)*nx+posx.
    const int posx1 = okxm ? 1 : 0;
    const int posy1 = okym ? 1 : 0;
    const int posz1 = okzm ? 1 : 0;
    const int posyS = okym ? 0 : 1;
    const int poszS = okzm ? 0 : 1;
    const int base00 = (posz1 * ny + posy1) * nx;
    const int baseY  = (posz1 * ny + posyS) * nx;
    const int baseZ  = (poszS * ny + posy1) * nx;
    const int baseYZ = (poszS * ny + posyS) * nx;

    // x bucket windows (conservative supersets)
    int blo0 = (int)floorf((pix - 0.3f - EPSB) * 256.0f); if (blo0 < 0) blo0 = 0;
    int bhi0 = (int)floorf((pix + 0.3f + EPSB) * 256.0f); if (bhi0 > 255) bhi0 = 255;
    int blo1 = (int)floorf((pix + 0.7f - EPSB) * 256.0f);
    if (blo1 > 255) blo1 = 255; if (blo1 < 0) blo1 = 0;
    int bhi2 = (int)floorf((pix - 0.7f + EPSB) * 256.0f);
    if (bhi2 > 255) bhi2 = 255; if (bhi2 < 0) bhi2 = 0;

    unsigned* __restrict__ rmask = s_mask[r];

    // ---- Discovery: order-free; hits -> flat slot bitmask via atomicOr ----
#pragma unroll
    for (int s = 0; s < 3; s++) {
        bool sval; float fsx; int posx, kb0, kb1; bool selfchk;
        if (s == 0)      { sval = true; fsx =  0.0f; posx = posx1;  kb0 = blo0; kb1 = bhi0; selfchk = true;  }
        else if (s == 1) { sval = okxm; fsx = -1.0f; posx = 0;      kb0 = blo1; kb1 = 255;  selfchk = false; }
        else             { sval = okxp; fsx =  1.0f; posx = nx - 1; kb0 = 0;    kb1 = bhi2; selfchk = false; }
        if (!sval) continue;
        unsigned* __restrict__ m00 = rmask + ((base00 + posx) << 6);
        unsigned* __restrict__ mY  = rmask + ((baseY  + posx) << 6);
        unsigned* __restrict__ mZ  = rmask + ((baseZ  + posx) << 6);
        unsigned* __restrict__ mYZ = rmask + ((baseYZ + posx) << 6);
        const int k0 = g_bstart[kb0];
        const int k1 = g_bstart[kb1 + 1];

        for (int base = k0 + q * 32; base < k1; base += WARPS_PER_ROW * 32) {
            const int k = base + lane;
            const bool val = (k < k1);
            const float4 p = g_sorted[val ? k : k0];
            const int jorig = __float_as_int(p.w);
            const int jw = jorig >> 5;
            const unsigned jb = 1u << (jorig & 31);
            // Exact reference rounding: ((p_j + s) - p_i), plain mul/add, no FMA.
            const float dx  = __fadd_rn(__fadd_rn(p.x, fsx), -pix);
            const float dx2 = __fmul_rn(dx, dx);
            const float dy0 = __fadd_rn(p.y, -piy);
            const float dz0 = __fadd_rn(p.z, -piz);
            const float dy0s = __fmul_rn(dy0, dy0);
            const float dz0s = __fmul_rn(dz0, dz0);
            float dy1s = 0.0f, dz1s = 0.0f;
            if (hy) {
                const float dy1 = __fadd_rn(__fadd_rn(p.y, fy), -piy);
                dy1s = __fmul_rn(dy1, dy1);
            }
            if (hz) {
                const float dz1 = __fadd_rn(__fadd_rn(p.z, fz), -piz);
                dz1s = __fmul_rn(dz1, dz1);
            }
            {
                const float d2 = __fadd_rn(__fadd_rn(dx2, dy0s), dz0s);
                if (val && d2 <= CUT2 && !(selfchk && jorig == i))
                    atomicOr(&m00[jw], jb);
            }
            if (hy) {
                const float d2 = __fadd_rn(__fadd_rn(dx2, dy1s), dz0s);
                if (val && d2 <= CUT2) atomicOr(&mY[jw], jb);
                if (hz) {
                    const float d2b = __fadd_rn(__fadd_rn(dx2, dy1s), dz1s);
                    if (val && d2b <= CUT2) atomicOr(&mYZ[jw], jb);
                }
            }
            if (hz) {
                const float d2 = __fadd_rn(__fadd_rn(dx2, dy0s), dz1s);
                if (val && d2 <= CUT2) atomicOr(&mZ[jw], jb);
            }
        }
    }
    __syncthreads();

    // ---- Count: contiguous popc sweep over this warp's span ----
    const int myt0 = q * nA * 16;
    const int myt1 = myt0 + nA * 16;
    int cnt = 0;
    for (int t = myt0 + lane; t < myt1; t += 32) cnt += __popc(rmask[t]);
#pragma unroll
    for (int d = 16; d; d >>= 1) cnt += __shfl_xor_sync(0xFFFFFFFFu, cnt, d);
    if (lane == 0) s_wcnt[r][q] = cnt;
    __syncthreads();

    int base = 0, rowTotal = 0;
#pragma unroll
    for (int q2 = 0; q2 < WARPS_PER_ROW; q2++) {
        const int cc = s_wcnt[r][q2];
        if (q2 < q) base += cc;
        rowTotal += cc;
    }

    // ---- Emit phase 1: flat ordered bit expansion -> 16-bit codes in smem ----
    {
        unsigned short* __restrict__ rstage = s_stage[r];
        const unsigned short* __restrict__ ctab = s_ccode[r];
        int off = base;
        for (int tg = myt0; tg < myt1; tg += 32) {
            const int t = tg + lane;
            const bool tv = (t < myt1);
            unsigned word = tv ? rmask[t] : 0u;
            const int ccode = tv ? (int)ctab[t >> 6] : 0;
            const int jbase = (t & 63) << 5;
            const int pc = __popc(word);
            int ex = pc;
#pragma unroll
            for (int d = 1; d < 32; d <<= 1) {
                const int tt = __shfl_up_sync(0xFFFFFFFFu, ex, d);
                if (lane >= d) ex += tt;
            }
            int myoff = off + ex - pc;
            while (word) {
                const int bit = __ffs(word) - 1;
                word &= word - 1;
                if (myoff < KCAP)
                    rstage[myoff] = (unsigned short)(ccode | (jbase + bit));
                myoff++;
            }
            off += __shfl_sync(0xFFFFFFFFu, ex, 31);
        }
    }
    __syncthreads();

    // ---- Emit phase 2: coalesced decode + fused tail fill ----
    float* __restrict__ out_neigh = out + (size_t)i * KCAP;
    float* __restrict__ out_cells = out + (size_t)NPTS * KCAP + (size_t)i * KCAP * 3;
    const unsigned short* __restrict__ rstage = s_stage[r];
    const int rowTid = tid & 127;
    const int filled = (rowTotal < KCAP) ? rowTotal : KCAP;
    for (int e = rowTid; e < KCAP; e += 128) {
        float vn, c0, c1, c2;
        if (e < filled) {
            const int code = rstage[e];
            const int j = code & 2047;
            const int c = code >> 11;
            vn = (float)j;
            c0 = (float)(c % 3 - 1);
            c1 = (float)((c / 3) % 3 - 1);
            c2 = (float)(c / 9 - 1);
        } else {
            vn = -1.0f; c0 = 1.0f; c1 = 1.0f; c2 = 1.0f;
        }
        out_neigh[e]         = vn;
        out_cells[3 * e]     = c0;
        out_cells[3 * e + 1] = c1;
        out_cells[3 * e + 2] = c2;
    }
    if (q == 0 && lane == 0) {
        atomicMax((int*)(out + MAX_OFFSET), __float_as_int((float)rowTotal));
    }

    // ---- Self-reset for next launch/replay (last finishing block) ----
    __syncthreads();
    if (tid == 0) {
        const int d = atomicAdd(&g_done, 1);
        if (d == (int)gridDim.x - 1) {
            g_flag = 0;
            g_done = 0;
            __threadfence();
        }
    }
}

extern "C" void kernel_launch(void* const* d_in, const int* in_sizes, int n_in,
                              void* d_out, int out_size) {
    const float* pos = (const float*)d_in[0];
    float* out = (float*)d_out;
    pb_fused_kernel<<<NPTS / ROWS_PER_BLOCK, NTHREADS>>>(pos, out);
}